// round 14
// baseline (speedup 1.0000x reference)
#include <cuda_runtime.h>

// Problem constants
#define PP 12
#define BB 4
#define KSTEP 12
#define TE_DEPTH 168
#define NUM_CELLS 1024   // 32*32
#define PQ 24            // P + Q

// Output layout (tuple flattened, row-major each):
#define OFF_Y    0
#define OFF_X    4096
#define OFF_T    53248
#define OFF_R    446464
#define OFF_RES  495616

// Dynamic smem layout (floats):
//  tp    @ 0      : 8 planes of 34x34 (9248)
//  xs    @ 9248   : 2 buffers of 34x34 (2312)   [tp+xs zeroed together: 11560]
//  stage @ 11560  : up to 192*13 this-CTA's-sixth results staging (2496)
//  wte_s @ 14056  : Wt[0:168] rows (1344)
//  wr_s  @ 15400  : Wr[0:168] (168)
//  wb_s  @ 15568  : Wb[0:168] (168)
#define TP_OFF    0
#define XS_OFF    9248
#define STG_OFF   11560
#define WTE_OFF   14056
#define WR_OFF    15400
#define WB_OFF    15568
#define SMEM_FLOATS 15736   // 62944 B  (x2 CTAs/SM = 125888 B, fits 228KB carveout)

// Six CTAs per (b,p) plane: all compute the full plane (cheap, duplicated),
// each stores only its sixth of every output. grid = 48*6 = 288 ≈ 2 CTAs/SM
// (296 slots on 148 SMs -> single wave). Co-resident CTAs interleave their
// serial BAR->LDS chains, hiding barrier latency.
// Warp-aligned sixths: sizes 192,192,160,160,160,160 cells.

__global__ __launch_bounds__(1024, 2) void rwr_kernel(
    const float* __restrict__ X,
    const int*   __restrict__ TE,
    const float* __restrict__ Wt,   // (1192, 8)
    const float* __restrict__ Wr,   // (1192, 1)
    const float* __restrict__ Wb,   // (1192, 1)
    float*       __restrict__ out)
{
    extern __shared__ __align__(16) float sm[];
    float* tp    = sm + TP_OFF;     // tp[d*1156 + r*34 + c]
    float* xs    = sm + XS_OFF;     // xs[buf*1156 + r*34 + c]
    float* stage = sm + STG_OFF;
    float* wte_s = sm + WTE_OFF;
    float* wr_s  = sm + WR_OFF;
    float* wb_s  = sm + WB_OFF;

    const int bp   = blockIdx.x / 6;    // 0..47
    const int part = blockIdx.x % 6;    // which sixth of outputs this CTA owns
    const int b    = bp / PP;
    const int p    = bp % PP;
    const int cell = threadIdx.x;       // 0..1023
    const int h    = cell >> 5;
    const int w    = cell & 31;

    const int base  = (part < 2) ? part * 192 : 384 + (part - 2) * 160;
    const int ncell = (part < 2) ? 192 : 160;
    const bool mine = (cell >= base) && (cell < base + ncell);   // warp-uniform

    // ---- issue ALL independent global loads at cycle 0 (max MLP) ----
    const float x0 = X[bp * NUM_CELLS + cell];
    const int te_day  = TE[(b * PQ + p) * 2 + 0];
    const int te_hour = TE[(b * PQ + p) * 2 + 1];
    const int cr = TE_DEPTH + cell;

    const float4* wc4 = reinterpret_cast<const float4*>(Wt + (size_t)cr * 8);
    const float4 wc_lo = wc4[0];
    const float4 wc_hi = wc4[1];
    const float wr_c = Wr[cr];
    const float wb_c = Wb[cr];

    // speculative te-block load -> smem (independent of TE value)
    if (cell < 420) {
        float4 v;
        if (cell < 336)      v = reinterpret_cast<const float4*>(Wt)[cell];
        else if (cell < 378) v = reinterpret_cast<const float4*>(Wr)[cell - 336];
        else                 v = reinterpret_cast<const float4*>(Wb)[cell - 378];
        float4* dst;
        if (cell < 336)      dst = reinterpret_cast<float4*>(wte_s) + cell;
        else if (cell < 378) dst = reinterpret_cast<float4*>(wr_s) + (cell - 336);
        else                 dst = reinterpret_cast<float4*>(wb_s) + (cell - 378);
        *dst = v;
    }

    // ---- full float4 zero of tp + xs (2890 float4) ----
    {
        float4* z4 = reinterpret_cast<float4*>(sm);
        const float4 zv = make_float4(0.f, 0.f, 0.f, 0.f);
        z4[cell] = zv;
        z4[cell + 1024] = zv;
        if (cell < 842) z4[cell + 2048] = zv;
    }

    __syncthreads();   // BAR#1: te-block resident + zero done

    // ---- read te row from smem (no second DRAM trip) ----
    const int te = te_day * 24 + te_hour;            // < 168
    const float4 wt_lo = reinterpret_cast<const float4*>(wte_s)[te * 2];
    const float4 wt_hi = reinterpret_cast<const float4*>(wte_s)[te * 2 + 1];
    const float wr_te = wr_s[te];
    const float wb_te = wb_s[te];

    // ---- softmax over 8 dirs (fast math; logits tiny, skip max-sub) ----
    float e[8], s = 0.f;
    e[0] = __expf(wt_lo.x + wc_lo.x);  e[1] = __expf(wt_lo.y + wc_lo.y);
    e[2] = __expf(wt_lo.z + wc_lo.z);  e[3] = __expf(wt_lo.w + wc_lo.w);
    e[4] = __expf(wt_hi.x + wc_hi.x);  e[5] = __expf(wt_hi.y + wc_hi.y);
    e[6] = __expf(wt_hi.z + wc_hi.z);  e[7] = __expf(wt_hi.w + wc_hi.w);
    #pragma unroll
    for (int d = 0; d < 8; d++) s += e[d];
    const float inv_s = __fdividef(1.0f, s);
    float tpv[8];
    #pragma unroll
    for (int d = 0; d < 8; d++) tpv[d] = e[d] * inv_s;

    const float rz = wr_te + wr_c;
    const float restart = __fdividef(1.0f, 1.0f + __expf(-rz));
    const float one_m_r = 1.0f - restart;
    const float bias = (wb_te + wb_c) * x0;

    // ---- static outputs: ONLY this CTA's sixth ----
    if (mine) {
        float4* t4 = reinterpret_cast<float4*>(out + OFF_T + (size_t)(bp * NUM_CELLS + cell) * 8);
        t4[0] = make_float4(tpv[0], tpv[1], tpv[2], tpv[3]);
        t4[1] = make_float4(tpv[4], tpv[5], tpv[6], tpv[7]);
        out[OFF_R + bp * NUM_CELLS + cell] = restart;
    }

    // ---- fill tp interior + x0 into xs buf0 + stage[0] (pre-BAR#2) ----
    const int ctr = (h + 1) * 34 + (w + 1);
    #pragma unroll
    for (int d = 0; d < 8; d++) tp[d * 1156 + ctr] = tpv[d];

    float* const xc0 = xs + ctr;          // buf 0 center
    float* const xc1 = xs + 1156 + ctr;   // buf 1 center
    float* sp = stage + (cell - base) * 13;   // per-cell stage pointer (local sixth)

    xc0[0] = x0;
    if (mine) sp[0] = x0;

    __syncthreads();   // BAR#2: tp + xs buf0 ready

    // DIRS d: 0:(-1,-1) 1:(-1,0) 2:(-1,1) 3:(0,-1) 4:(0,1) 5:(1,-1) 6:(1,0) 7:(1,1)
    float w_in[8];
    {
        const float* tpc = tp + ctr;
        w_in[0] = tpc[0 * 1156 - 35];
        w_in[1] = tpc[1 * 1156 - 34];
        w_in[2] = tpc[2 * 1156 - 33];
        w_in[3] = tpc[3 * 1156 -  1];
        w_in[4] = tpc[4 * 1156 +  1];
        w_in[5] = tpc[5 * 1156 + 33];
        w_in[6] = tpc[6 * 1156 + 34];
        w_in[7] = tpc[7 * 1156 + 35];
    }

    // ---- peeled iteration 0 (reads buf0, covered by BAR#2) ----
    float x;
    {
        float a0 = xc0[-35] * w_in[0];
        float a1 = xc0[-34] * w_in[1];
        float a2 = xc0[-33] * w_in[2];
        float a3 = xc0[ -1] * w_in[3];
        a0 = fmaf(xc0[  1], w_in[4], a0);
        a1 = fmaf(xc0[ 33], w_in[5], a1);
        a2 = fmaf(xc0[ 34], w_in[6], a2);
        a3 = fmaf(xc0[ 35], w_in[7], a3);
        const float xt = (a0 + a1) + (a2 + a3);
        x = fmaf(one_m_r, xt, fmaf(restart, x0, bias));
        if (mine) sp[1] = x;
    }

    // ---- iterations 1..11: store -> BAR -> stencil ----
    #pragma unroll
    for (int k = 1; k < KSTEP; k++) {
        float* const xb = (k & 1) ? xc1 : xc0;
        xb[0] = x;
        __syncthreads();
        float a0 = xb[-35] * w_in[0];
        float a1 = xb[-34] * w_in[1];
        float a2 = xb[-33] * w_in[2];
        float a3 = xb[ -1] * w_in[3];
        a0 = fmaf(xb[  1], w_in[4], a0);
        a1 = fmaf(xb[ 33], w_in[5], a1);
        a2 = fmaf(xb[ 34], w_in[6], a2);
        a3 = fmaf(xb[ 35], w_in[7], a3);
        const float xt = (a0 + a1) + (a2 + a3);
        x = fmaf(one_m_r, xt, fmaf(restart, x, bias));
        if (mine) sp[k + 1] = x;
    }

    // final state x + Y: only this CTA's sixth
    if (mine) {
        out[OFF_X + bp * NUM_CELLS + cell] = x;
        if (p == PP - 1)
            out[OFF_Y + b * NUM_CELLS + cell] = x;
    }

    // ---- one barrier, then dump ONLY this sixth (624 or 520 float4) ----
    __syncthreads();
    const int n4 = (ncell * 13) >> 2;          // 624 or 520
    const float4* s4 = reinterpret_cast<const float4*>(stage);
    float4* o4 = reinterpret_cast<float4*>(out + OFF_RES + (size_t)bp * (NUM_CELLS * 13))
                 + ((base * 13) >> 2);
    if (cell < n4) o4[cell] = s4[cell];
}

extern "C" void kernel_launch(void* const* d_in, const int* in_sizes, int n_in,
                              void* d_out, int out_size) {
    const float* X  = (const float*)d_in[0];
    const int*   TE = (const int*)d_in[1];
    const float* Wt = (const float*)d_in[2];
    const float* Wr = (const float*)d_in[3];
    const float* Wb = (const float*)d_in[4];
    float* out = (float*)d_out;
    const int smem_bytes = SMEM_FLOATS * 4;   // 62944 B
    cudaFuncSetAttribute(rwr_kernel, cudaFuncAttributeMaxDynamicSharedMemorySize, smem_bytes);
    rwr_kernel<<<BB * PP * 6, 1024, smem_bytes>>>(X, TE, Wt, Wr, Wb, out);
}

// round 15
// speedup vs baseline: 1.2270x; 1.2270x over previous
#include <cuda_runtime.h>

// Problem constants
#define PP 12
#define BB 4
#define KSTEP 12
#define TE_DEPTH 168
#define NUM_CELLS 1024   // 32*32
#define PQ 24            // P + Q

// Output layout (tuple flattened, row-major each):
#define OFF_Y    0
#define OFF_X    4096
#define OFF_T    53248
#define OFF_R    446464
#define OFF_RES  495616

// Dynamic smem layout (floats):
//  tp    @ 0      : 8 planes of 34x34 (9248), row stride 34
//  xs    @ 9248   : 2 buffers of 34 rows x 36 stride (2448); cells at cols 2..33
//                   so even pair bases are 8B-aligned for LDS.64/STS.64
//  stage @ 11696  : up to 384*13 this-CTA's-part results staging (4992)
//  wte_s @ 16688  : Wt[0:168] rows (1344)
//  wr_s  @ 18032  : Wr[0:168] (168)
//  wb_s  @ 18200  : Wb[0:168] (168)
#define TP_OFF    0
#define XS_OFF    9248
#define XS_STRIDE 36
#define XS_SIZE   (34 * XS_STRIDE)        // 1224
#define STG_OFF   (XS_OFF + 2 * XS_SIZE)  // 11696
#define WTE_OFF   16688
#define WR_OFF    18032
#define WB_OFF    18200
#define SMEM_FLOATS 18368   // 73472 B

// Three CTAs per (b,p) plane (grid = 144 ≈ 1 CTA/SM): all compute the full
// plane, each stores only its part. Parts warp-aligned for 512 threads/2-cell:
// part0 cells [0,384), part1 [384,768), part2 [768,1024).

__global__ __launch_bounds__(512, 1) void rwr_kernel(
    const float* __restrict__ X,
    const int*   __restrict__ TE,
    const float* __restrict__ Wt,   // (1192, 8)
    const float* __restrict__ Wr,   // (1192, 1)
    const float* __restrict__ Wb,   // (1192, 1)
    float*       __restrict__ out)
{
    extern __shared__ __align__(16) float sm[];
    float* tp    = sm + TP_OFF;
    float* xs    = sm + XS_OFF;
    float* stage = sm + STG_OFF;
    float* wte_s = sm + WTE_OFF;
    float* wr_s  = sm + WR_OFF;
    float* wb_s  = sm + WB_OFF;

    const int bp   = blockIdx.x / 3;    // 0..47
    const int part = blockIdx.x % 3;
    const int b    = bp / PP;
    const int p    = bp % PP;
    const int tid  = threadIdx.x;       // 0..511
    const int h    = tid >> 4;          // row 0..31
    const int wp   = (tid & 15) << 1;   // even col 0..30
    const int cell0 = (h << 5) + wp;

    const int base  = part * 384;                    // 0 / 384 / 768
    const int ncell = (part == 2) ? 256 : 384;
    const bool mine = (cell0 >= base) && (cell0 < base + ncell);  // warp-uniform

    // ---- issue ALL independent global loads at cycle 0 (max MLP) ----
    const float2 xin = *reinterpret_cast<const float2*>(X + bp * NUM_CELLS + cell0);
    const int te_day  = TE[(b * PQ + p) * 2 + 0];
    const int te_hour = TE[(b * PQ + p) * 2 + 1];
    const int cr0 = TE_DEPTH + cell0;

    const float4* wc4 = reinterpret_cast<const float4*>(Wt + (size_t)cr0 * 8);
    const float4 wca_lo = wc4[0], wca_hi = wc4[1];
    const float4 wcb_lo = wc4[2], wcb_hi = wc4[3];
    const float2 wrc = *reinterpret_cast<const float2*>(Wr + cr0);
    const float2 wbc = *reinterpret_cast<const float2*>(Wb + cr0);

    // speculative te-block load -> smem (420 float4)
    if (tid < 420) {
        float4 v;
        if (tid < 336)      v = reinterpret_cast<const float4*>(Wt)[tid];
        else if (tid < 378) v = reinterpret_cast<const float4*>(Wr)[tid - 336];
        else                v = reinterpret_cast<const float4*>(Wb)[tid - 378];
        float4* dst;
        if (tid < 336)      dst = reinterpret_cast<float4*>(wte_s) + tid;
        else if (tid < 378) dst = reinterpret_cast<float4*>(wr_s) + (tid - 336);
        else                dst = reinterpret_cast<float4*>(wb_s) + (tid - 378);
        *dst = v;
    }

    // ---- full float4 zero of tp + xs (11696 floats = 2924 float4) ----
    {
        float4* z4 = reinterpret_cast<float4*>(sm);
        const float4 zv = make_float4(0.f, 0.f, 0.f, 0.f);
        #pragma unroll
        for (int i = 0; i < 6; i++) {
            const int idx = tid + i * 512;
            if (idx < 2924) z4[idx] = zv;
        }
    }

    __syncthreads();   // BAR#1: te-block resident + zero done

    // ---- read te row from smem ----
    const int te = te_day * 24 + te_hour;            // < 168
    const float4 wt_lo = reinterpret_cast<const float4*>(wte_s)[te * 2];
    const float4 wt_hi = reinterpret_cast<const float4*>(wte_s)[te * 2 + 1];
    const float wr_te = wr_s[te];
    const float wb_te = wb_s[te];

    // ---- per-cell (x2) softmax, sigmoid restart, bias ----
    const float xv_in[2] = {xin.x, xin.y};
    float tpv[2][8], restart[2], omr[2], bias[2];
    #pragma unroll
    for (int j = 0; j < 2; j++) {
        const float4 lo = j ? wcb_lo : wca_lo;
        const float4 hi = j ? wcb_hi : wca_hi;
        float e[8], s = 0.f;
        e[0] = __expf(wt_lo.x + lo.x);  e[1] = __expf(wt_lo.y + lo.y);
        e[2] = __expf(wt_lo.z + lo.z);  e[3] = __expf(wt_lo.w + lo.w);
        e[4] = __expf(wt_hi.x + hi.x);  e[5] = __expf(wt_hi.y + hi.y);
        e[6] = __expf(wt_hi.z + hi.z);  e[7] = __expf(wt_hi.w + hi.w);
        #pragma unroll
        for (int d = 0; d < 8; d++) s += e[d];
        const float inv_s = __fdividef(1.0f, s);
        #pragma unroll
        for (int d = 0; d < 8; d++) tpv[j][d] = e[d] * inv_s;

        const float rz = wr_te + (j ? wrc.y : wrc.x);
        restart[j] = __fdividef(1.0f, 1.0f + __expf(-rz));
        omr[j] = 1.0f - restart[j];
        bias[j] = (wb_te + (j ? wbc.y : wbc.x)) * xv_in[j];
    }

    // ---- static outputs: ONLY this CTA's part ----
    if (mine) {
        #pragma unroll
        for (int j = 0; j < 2; j++) {
            float4* t4 = reinterpret_cast<float4*>(out + OFF_T + (size_t)(bp * NUM_CELLS + cell0 + j) * 8);
            t4[0] = make_float4(tpv[j][0], tpv[j][1], tpv[j][2], tpv[j][3]);
            t4[1] = make_float4(tpv[j][4], tpv[j][5], tpv[j][6], tpv[j][7]);
        }
        *reinterpret_cast<float2*>(out + OFF_R + bp * NUM_CELLS + cell0) =
            make_float2(restart[0], restart[1]);
    }

    // ---- fill tp interior + x0 pair into xs buf0 + stage[0] (pre-BAR#2) ----
    const int tctr = (h + 1) * 34 + (wp + 1);
    #pragma unroll
    for (int d = 0; d < 8; d++) {
        tp[d * 1156 + tctr]     = tpv[0][d];
        tp[d * 1156 + tctr + 1] = tpv[1][d];
    }

    const int ctr = (h + 1) * XS_STRIDE + (wp + 2);   // even -> 8B aligned
    float* sp = stage + (cell0 - base) * 13;          // local part offset

    *reinterpret_cast<float2*>(&xs[ctr]) = make_float2(xv_in[0], xv_in[1]);
    if (mine) { sp[0] = xv_in[0]; sp[13] = xv_in[1]; }

    __syncthreads();   // BAR#2: tp + xs buf0 ready

    // incoming weights: DIRS d offsets in 34-stride tp
    const int DOF[8] = {-35, -34, -33, -1, 1, 33, 34, 35};
    float w_in[2][8];
    #pragma unroll
    for (int d = 0; d < 8; d++) {
        w_in[0][d] = tp[d * 1156 + tctr + DOF[d]];
        w_in[1][d] = tp[d * 1156 + tctr + 1 + DOF[d]];
    }

    float x0v = xv_in[0], x1v = xv_in[1];

    // ---- iterations 0..11; iter 0 reads pre-stored buf0 (BAR#2 covers) ----
    #pragma unroll
    for (int k = 0; k < KSTEP; k++) {
        float* xb = xs + (k & 1) * XS_SIZE;
        if (k > 0) {
            *reinterpret_cast<float2*>(&xb[ctr]) = make_float2(x0v, x1v);
            __syncthreads();
        }

        const float  tL = xb[ctr - XS_STRIDE - 1];
        const float2 tC = *reinterpret_cast<const float2*>(&xb[ctr - XS_STRIDE]);
        const float  tR = xb[ctr - XS_STRIDE + 2];
        const float  mL = xb[ctr - 1];
        const float  mR = xb[ctr + 2];
        const float  bL = xb[ctr + XS_STRIDE - 1];
        const float2 bC = *reinterpret_cast<const float2*>(&xb[ctr + XS_STRIDE]);
        const float  bR = xb[ctr + XS_STRIDE + 2];

        float a0 = tL   * w_in[0][0];
        float a1 = tC.x * w_in[0][1];
        float a2 = tC.y * w_in[0][2];
        float a3 = mL   * w_in[0][3];
        a0 = fmaf(x1v,  w_in[0][4], a0);
        a1 = fmaf(bL,   w_in[0][5], a1);
        a2 = fmaf(bC.x, w_in[0][6], a2);
        a3 = fmaf(bC.y, w_in[0][7], a3);
        const float xt0 = (a0 + a1) + (a2 + a3);

        float c0 = tC.x * w_in[1][0];
        float c1 = tC.y * w_in[1][1];
        float c2 = tR   * w_in[1][2];
        float c3 = x0v  * w_in[1][3];
        c0 = fmaf(mR,   w_in[1][4], c0);
        c1 = fmaf(bC.x, w_in[1][5], c1);
        c2 = fmaf(bC.y, w_in[1][6], c2);
        c3 = fmaf(bR,   w_in[1][7], c3);
        const float xt1 = (c0 + c1) + (c2 + c3);

        x0v = fmaf(omr[0], xt0, fmaf(restart[0], x0v, bias[0]));
        x1v = fmaf(omr[1], xt1, fmaf(restart[1], x1v, bias[1]));
        if (mine) { sp[k + 1] = x0v; sp[13 + k + 1] = x1v; }
    }

    // final state x + Y: only this CTA's part
    if (mine) {
        *reinterpret_cast<float2*>(out + OFF_X + bp * NUM_CELLS + cell0) = make_float2(x0v, x1v);
        if (p == PP - 1)
            *reinterpret_cast<float2*>(out + OFF_Y + b * NUM_CELLS + cell0) = make_float2(x0v, x1v);
    }

    // ---- one barrier, then dump ONLY this part (1248 / 1248 / 832 float4) ----
    __syncthreads();
    const int n4 = (ncell * 13) >> 2;
    const float4* s4 = reinterpret_cast<const float4*>(stage);
    float4* o4 = reinterpret_cast<float4*>(out + OFF_RES + (size_t)bp * (NUM_CELLS * 13))
                 + ((base * 13) >> 2);
    #pragma unroll
    for (int i = 0; i < 3; i++) {
        const int idx = tid + i * 512;
        if (idx < n4) o4[idx] = s4[idx];
    }
}

extern "C" void kernel_launch(void* const* d_in, const int* in_sizes, int n_in,
                              void* d_out, int out_size) {
    const float* X  = (const float*)d_in[0];
    const int*   TE = (const int*)d_in[1];
    const float* Wt = (const float*)d_in[2];
    const float* Wr = (const float*)d_in[3];
    const float* Wb = (const float*)d_in[4];
    float* out = (float*)d_out;
    const int smem_bytes = SMEM_FLOATS * 4;   // 73472 B
    cudaFuncSetAttribute(rwr_kernel, cudaFuncAttributeMaxDynamicSharedMemorySize, smem_bytes);
    rwr_kernel<<<BB * PP * 3, 512, smem_bytes>>>(X, TE, Wt, Wr, Wb, out);
}

// round 16
// speedup vs baseline: 1.4815x; 1.2074x over previous
#include <cuda_runtime.h>

// Problem constants
#define PP 12
#define BB 4
#define KSTEP 12
#define TE_DEPTH 168
#define NUM_CELLS 1024   // 32*32
#define PQ 24            // P + Q

// Output layout (tuple flattened, row-major each):
#define OFF_Y    0
#define OFF_X    4096
#define OFF_T    53248
#define OFF_R    446464
#define OFF_RES  495616

// Dynamic smem layout (floats):
//  tp    @ 0      : 8 planes of 34x34 (9248), row stride 34
//  xs    @ 9248   : 2 buffers of 34 rows x 36 stride (2448); cells at cols 2..33
//                   (even pair bases 8B-aligned for LDS.64/STS.64)
//  stage @ 11696  : 352*13 this-CTA's-third results staging (4576)
//  wte_s @ 16272  : Wt[0:168] rows (1344)
//  wr_s  @ 17616  : Wr[0:168] (168)
//  wb_s  @ 17784  : Wb[0:168] (168)
#define TP_OFF    0
#define XS_OFF    9248
#define XS_STRIDE 36
#define XS_SIZE   (34 * XS_STRIDE)        // 1224
#define STG_OFF   (XS_OFF + 2 * XS_SIZE)  // 11696
#define WTE_OFF   16272
#define WR_OFF    17616
#define WB_OFF    17784
#define SMEM_FLOATS 17952   // 71808 B

// Three CTAs per (b,p) plane (grid=144 ≈ 1 CTA/SM): all compute the full
// plane, each stores only its third (thirds row-aligned: 11/11/10 rows).
// Prologue + dump run at 1024 threads; the 12-step loop runs on warps 0-15
// only (512 threads, 2 adjacent cells/thread) using named barrier 1.

__global__ __launch_bounds__(1024, 1) void rwr_kernel(
    const float* __restrict__ X,
    const int*   __restrict__ TE,
    const float* __restrict__ Wt,   // (1192, 8)
    const float* __restrict__ Wr,   // (1192, 1)
    const float* __restrict__ Wb,   // (1192, 1)
    float*       __restrict__ out)
{
    extern __shared__ __align__(16) float sm[];
    float* tp    = sm + TP_OFF;
    float* xs    = sm + XS_OFF;
    float* stage = sm + STG_OFF;
    float* wte_s = sm + WTE_OFF;
    float* wr_s  = sm + WR_OFF;
    float* wb_s  = sm + WB_OFF;

    const int bp   = blockIdx.x / 3;    // 0..47
    const int part = blockIdx.x % 3;
    const int b    = bp / PP;
    const int p    = bp % PP;
    const int cell = threadIdx.x;       // 0..1023
    const int h    = cell >> 5;
    const int w    = cell & 31;

    const int base  = part * 352;                     // 0 / 352 / 704 (row-aligned)
    const int ncell = (part == 2) ? 320 : 352;
    const bool mine = (cell >= base) && (cell < base + ncell);   // warp-uniform

    // ---- issue ALL independent global loads at cycle 0 (max MLP, 32 warps) ----
    const float x0 = X[bp * NUM_CELLS + cell];
    const int te_day  = TE[(b * PQ + p) * 2 + 0];
    const int te_hour = TE[(b * PQ + p) * 2 + 1];
    const int cr = TE_DEPTH + cell;

    const float4* wc4 = reinterpret_cast<const float4*>(Wt + (size_t)cr * 8);
    const float4 wc_lo = wc4[0];
    const float4 wc_hi = wc4[1];
    const float wr_c = Wr[cr];
    const float wb_c = Wb[cr];

    // speculative te-block load -> smem (independent of TE value)
    if (cell < 420) {
        float4 v;
        if (cell < 336)      v = reinterpret_cast<const float4*>(Wt)[cell];
        else if (cell < 378) v = reinterpret_cast<const float4*>(Wr)[cell - 336];
        else                 v = reinterpret_cast<const float4*>(Wb)[cell - 378];
        float4* dst;
        if (cell < 336)      dst = reinterpret_cast<float4*>(wte_s) + cell;
        else if (cell < 378) dst = reinterpret_cast<float4*>(wr_s) + (cell - 336);
        else                 dst = reinterpret_cast<float4*>(wb_s) + (cell - 378);
        *dst = v;
    }

    // ---- full float4 zero of tp + xs (11696 floats = 2924 float4) ----
    {
        float4* z4 = reinterpret_cast<float4*>(sm);
        const float4 zv = make_float4(0.f, 0.f, 0.f, 0.f);
        z4[cell] = zv;
        z4[cell + 1024] = zv;
        if (cell < 876) z4[cell + 2048] = zv;
    }

    __syncthreads();   // BAR#1: te-block resident + zero done

    // ---- read te row from smem (no second DRAM trip) ----
    const int te = te_day * 24 + te_hour;            // < 168
    const float4 wt_lo = reinterpret_cast<const float4*>(wte_s)[te * 2];
    const float4 wt_hi = reinterpret_cast<const float4*>(wte_s)[te * 2 + 1];
    const float wr_te = wr_s[te];
    const float wb_te = wb_s[te];

    // ---- per-cell softmax (fast math; logits tiny, skip max-sub) ----
    float e[8], s = 0.f;
    e[0] = __expf(wt_lo.x + wc_lo.x);  e[1] = __expf(wt_lo.y + wc_lo.y);
    e[2] = __expf(wt_lo.z + wc_lo.z);  e[3] = __expf(wt_lo.w + wc_lo.w);
    e[4] = __expf(wt_hi.x + wc_hi.x);  e[5] = __expf(wt_hi.y + wc_hi.y);
    e[6] = __expf(wt_hi.z + wc_hi.z);  e[7] = __expf(wt_hi.w + wc_hi.w);
    #pragma unroll
    for (int d = 0; d < 8; d++) s += e[d];
    const float inv_s = __fdividef(1.0f, s);
    float tpv[8];
    #pragma unroll
    for (int d = 0; d < 8; d++) tpv[d] = e[d] * inv_s;

    const float rz = wr_te + wr_c;
    const float restart0 = __fdividef(1.0f, 1.0f + __expf(-rz));
    const float bias0 = (wb_te + wb_c) * x0;

    // ---- static outputs: ONLY this CTA's third (fire-and-forget) ----
    if (mine) {
        float4* t4 = reinterpret_cast<float4*>(out + OFF_T + (size_t)(bp * NUM_CELLS + cell) * 8);
        t4[0] = make_float4(tpv[0], tpv[1], tpv[2], tpv[3]);
        t4[1] = make_float4(tpv[4], tpv[5], tpv[6], tpv[7]);
        out[OFF_R + bp * NUM_CELLS + cell] = restart0;
        stage[(cell - base) * 13] = x0;
    }

    // ---- fill tp interior + x0 into xs buf0 (pre-BAR#2) ----
    const int tctr0 = (h + 1) * 34 + (w + 1);
    #pragma unroll
    for (int d = 0; d < 8; d++) tp[d * 1156 + tctr0] = tpv[d];
    xs[(h + 1) * XS_STRIDE + (w + 2)] = x0;      // buf 0

    // restart & bias planes for the loop warps: stash per-cell values in smem?
    // Not needed: loop threads recompute from their own pair cells below via
    // the same smem-resident W tables (cheap, avoids extra planes).

    __syncthreads();   // BAR#2: tp + xs buf0 + stage[0] ready

    // ================== LOOP: warps 0-15 only (512 threads) ==================
    if (cell < 512) {
        const int tid  = cell;              // 0..511
        const int lh   = tid >> 4;          // row 0..31
        const int lwp  = (tid & 15) << 1;   // even col 0..30
        const int c0   = (lh << 5) + lwp;   // pair base cell

        const bool lmine = (c0 >= base) && (c0 < base + ncell);
        float* sp = stage + (c0 - base) * 13;

        // per-pair params recomputed from smem tables (few MUFU ops)
        const int pcr = TE_DEPTH + c0;
        const float4* pw4 = reinterpret_cast<const float4*>(Wt + (size_t)pcr * 8);
        float rst[2], omr[2], bia[2], xv[2];
        xv[0] = X[bp * NUM_CELLS + c0];
        xv[1] = X[bp * NUM_CELLS + c0 + 1];
        #pragma unroll
        for (int j = 0; j < 2; j++) {
            const float rzj = wr_te + Wr[pcr + j];
            rst[j] = __fdividef(1.0f, 1.0f + __expf(-rzj));
            omr[j] = 1.0f - rst[j];
            bia[j] = (wb_te + Wb[pcr + j]) * xv[j];
        }
        (void)pw4;

        // incoming weights for both cells from tp planes
        const int tctr = (lh + 1) * 34 + (lwp + 1);
        const int DOF[8] = {-35, -34, -33, -1, 1, 33, 34, 35};
        float w_in[2][8];
        #pragma unroll
        for (int d = 0; d < 8; d++) {
            w_in[0][d] = tp[d * 1156 + tctr + DOF[d]];
            w_in[1][d] = tp[d * 1156 + tctr + 1 + DOF[d]];
        }

        const int ctr = (lh + 1) * XS_STRIDE + (lwp + 2);   // even -> 8B aligned

        #pragma unroll
        for (int k = 0; k < KSTEP; k++) {
            float* xb = xs + (k & 1) * XS_SIZE;
            if (k > 0) {
                *reinterpret_cast<float2*>(&xb[ctr]) = make_float2(xv[0], xv[1]);
                asm volatile("bar.sync 1, 512;" ::: "memory");
            }

            const float  tL = xb[ctr - XS_STRIDE - 1];
            const float2 tC = *reinterpret_cast<const float2*>(&xb[ctr - XS_STRIDE]);
            const float  tR = xb[ctr - XS_STRIDE + 2];
            const float  mL = xb[ctr - 1];
            const float  mR = xb[ctr + 2];
            const float  bL = xb[ctr + XS_STRIDE - 1];
            const float2 bC = *reinterpret_cast<const float2*>(&xb[ctr + XS_STRIDE]);
            const float  bR = xb[ctr + XS_STRIDE + 2];

            float a0 = tL   * w_in[0][0];
            float a1 = tC.x * w_in[0][1];
            float a2 = tC.y * w_in[0][2];
            float a3 = mL   * w_in[0][3];
            a0 = fmaf(xv[1], w_in[0][4], a0);
            a1 = fmaf(bL,    w_in[0][5], a1);
            a2 = fmaf(bC.x,  w_in[0][6], a2);
            a3 = fmaf(bC.y,  w_in[0][7], a3);
            const float xt0 = (a0 + a1) + (a2 + a3);

            float c0v = tC.x * w_in[1][0];
            float c1v = tC.y * w_in[1][1];
            float c2v = tR   * w_in[1][2];
            float c3v = xv[0] * w_in[1][3];
            c0v = fmaf(mR,   w_in[1][4], c0v);
            c1v = fmaf(bC.x, w_in[1][5], c1v);
            c2v = fmaf(bC.y, w_in[1][6], c2v);
            c3v = fmaf(bR,   w_in[1][7], c3v);
            const float xt1 = (c0v + c1v) + (c2v + c3v);

            xv[0] = fmaf(omr[0], xt0, fmaf(rst[0], xv[0], bia[0]));
            xv[1] = fmaf(omr[1], xt1, fmaf(rst[1], xv[1], bia[1]));
            if (lmine) { sp[k + 1] = xv[0]; sp[13 + k + 1] = xv[1]; }
        }

        // final state x + Y: only this CTA's third
        if (lmine) {
            *reinterpret_cast<float2*>(out + OFF_X + bp * NUM_CELLS + c0) =
                make_float2(xv[0], xv[1]);
            if (p == PP - 1)
                *reinterpret_cast<float2*>(out + OFF_Y + b * NUM_CELLS + c0) =
                    make_float2(xv[0], xv[1]);
        }
    }
    // warps 16-31 skip straight here.

    // ---- one full barrier, then 1024-thread coalesced dump of this third ----
    __syncthreads();
    const int n4 = (ncell * 13) >> 2;          // 1144 or 1040
    const float4* s4 = reinterpret_cast<const float4*>(stage);
    float4* o4 = reinterpret_cast<float4*>(out + OFF_RES + (size_t)bp * (NUM_CELLS * 13))
                 + ((base * 13) >> 2);
    if (cell < n4) o4[cell] = s4[cell];
    if (cell < n4 - 1024) o4[cell + 1024] = s4[cell + 1024];
}

extern "C" void kernel_launch(void* const* d_in, const int* in_sizes, int n_in,
                              void* d_out, int out_size) {
    const float* X  = (const float*)d_in[0];
    const int*   TE = (const int*)d_in[1];
    const float* Wt = (const float*)d_in[2];
    const float* Wr = (const float*)d_in[3];
    const float* Wb = (const float*)d_in[4];
    float* out = (float*)d_out;
    const int smem_bytes = SMEM_FLOATS * 4;   // 71808 B
    cudaFuncSetAttribute(rwr_kernel, cudaFuncAttributeMaxDynamicSharedMemorySize, smem_bytes);
    rwr_kernel<<<BB * PP * 3, 1024, smem_bytes>>>(X, TE, Wt, Wr, Wb, out);
}